// round 1
// baseline (speedup 1.0000x reference)
#include <cuda_runtime.h>

#define NGT   8000
#define NSAMP 4000
#define TILE  256
#define PARTITIONABLE 1   // jax_threefry_partitionable=True (jax >= 0.5 default)

static __device__ double g_loss;
static __device__ float  g_samp[3][NSAMP * 3];
static __device__ int    g_imin[3][10242];

struct Params {
  const float* gt;  const float* gtn;
  const float* pred[3]; const float* bef[3];
  const int*   edges[3]; const int* faces[3]; const int* lap[3];
  float* out;
};

// ---------------- threefry2x32 (exact JAX block) ----------------
__device__ __forceinline__ void tf(unsigned k0, unsigned k1,
                                   unsigned x0, unsigned x1,
                                   unsigned& o0, unsigned& o1) {
  unsigned ks2 = k0 ^ k1 ^ 0x1BD11BDAu;
  x0 += k0; x1 += k1;
#define R_(r) { x0 += x1; x1 = (x1 << (r)) | (x1 >> (32 - (r))); x1 ^= x0; }
  R_(13) R_(15) R_(26) R_(6)  x0 += k1;  x1 += ks2 + 1u;
  R_(17) R_(29) R_(16) R_(24) x0 += ks2; x1 += k0  + 2u;
  R_(13) R_(15) R_(26) R_(6)  x0 += k0;  x1 += k1  + 3u;
  R_(17) R_(29) R_(16) R_(24) x0 += k1;  x1 += ks2 + 4u;
  R_(13) R_(15) R_(26) R_(6)  x0 += ks2; x1 += k0  + 5u;
#undef R_
  o0 = x0; o1 = x1;
}

__device__ __forceinline__ int vb_of(int b) { return b == 0 ? 642 : (b == 1 ? 2562 : 10242); }

// block-level weighted-sum -> single double atomic (blockDim.x == 128)
__device__ __forceinline__ void block_add(double v) {
  #pragma unroll
  for (int o = 16; o; o >>= 1) v += __shfl_down_sync(0xffffffffu, v, o);
  __shared__ double ws[4];
  int lane = threadIdx.x & 31, w = threadIdx.x >> 5;
  if (lane == 0) ws[w] = v;
  __syncthreads();
  if (w == 0) {
    double t = (lane < 4) ? ws[lane] : 0.0;
    t += __shfl_down_sync(0xffffffffu, t, 2);
    t += __shfl_down_sync(0xffffffffu, t, 1);
    if (lane == 0) atomicAdd(&g_loss, t);
  }
}

__global__ void k_init() { g_loss = 0.0; }

// ---------------- triangle sampling with exact JAX PRNG ----------------
__global__ void k_sample(Params P) {
  int b = blockIdx.z;
  int i = blockIdx.x * blockDim.x + threadIdx.x;
  if (i >= NSAMP) return;
  int Vb = vb_of(b);
  unsigned span = 2u * (unsigned)Vb;   // faces.shape[0]

  // key_b = fold_in(key(42), b) = block((0,42),(0,b))
  unsigned kb0, kb1; tf(0u, 42u, 0u, (unsigned)b, kb0, kb1);
  unsigned hi, lo, u0b, u1b;
#if PARTITIONABLE
  unsigned kf0, kf1, ku0, ku1, k10, k11, k20, k21, t0, t1;
  tf(kb0, kb1, 0u, 0u, kf0, kf1);   // kf = split(key_b)[0]
  tf(kb0, kb1, 0u, 1u, ku0, ku1);   // kb = split(key_b)[1]
  tf(kf0, kf1, 0u, 0u, k10, k11);   // k1 = split(kf)[0]
  tf(kf0, kf1, 0u, 1u, k20, k21);   // k2 = split(kf)[1]
  tf(k10, k11, 0u, (unsigned)i, t0, t1);            hi  = t0 ^ t1;
  tf(k20, k21, 0u, (unsigned)i, t0, t1);            lo  = t0 ^ t1;
  tf(ku0, ku1, 0u, (unsigned)(2 * i),     t0, t1);  u0b = t0 ^ t1;
  tf(ku0, ku1, 0u, (unsigned)(2 * i + 1), t0, t1);  u1b = t0 ^ t1;
#else
  unsigned a0, a1, c0, c1, t0, t1;
  tf(kb0, kb1, 0u, 2u, a0, a1);
  tf(kb0, kb1, 1u, 3u, c0, c1);
  unsigned kf0 = a0, kf1 = c0, ku0 = a1, ku1 = c1;
  tf(kf0, kf1, 0u, 2u, a0, a1);
  tf(kf0, kf1, 1u, 3u, c0, c1);
  unsigned k10 = a0, k11 = c0, k20 = a1, k21 = c1;
  if (i < NSAMP / 2) { tf(k10, k11, (unsigned)i, (unsigned)(i + NSAMP / 2), t0, t1); hi = t0; }
  else               { tf(k10, k11, (unsigned)(i - NSAMP / 2), (unsigned)i, t0, t1); hi = t1; }
  if (i < NSAMP / 2) { tf(k20, k21, (unsigned)i, (unsigned)(i + NSAMP / 2), t0, t1); lo = t0; }
  else               { tf(k20, k21, (unsigned)(i - NSAMP / 2), (unsigned)i, t0, t1); lo = t1; }
  int tt = 2 * i;
  if (tt < NSAMP) { tf(ku0, ku1, (unsigned)tt, (unsigned)(tt + NSAMP), t0, t1); u0b = t0; }
  else            { tf(ku0, ku1, (unsigned)(tt - NSAMP), (unsigned)tt, t0, t1); u0b = t1; }
  tt = 2 * i + 1;
  if (tt < NSAMP) { tf(ku0, ku1, (unsigned)tt, (unsigned)(tt + NSAMP), t0, t1); u1b = t0; }
  else            { tf(ku0, ku1, (unsigned)(tt - NSAMP), (unsigned)tt, t0, t1); u1b = t1; }
#endif
  // jax randint: double-draw remainder trick
  unsigned m = 65536u % span; m = (m * m) % span;
  unsigned off = ((hi % span) * m + (lo % span)) % span;
  int fidx = (int)off;
  // jax uniform [0,1): mantissa-fill trick
  float u0 = __uint_as_float((u0b >> 9) | 0x3F800000u) - 1.0f;
  float u1 = __uint_as_float((u1b >> 9) | 0x3F800000u) - 1.0f;
  float r1 = sqrtf(u0);
  float w0 = 1.0f - r1, w1 = r1 * (1.0f - u1), w2 = r1 * u1;

  const int* f = P.faces[b] + 3 * fidx;
  const float* pr = P.pred[b];
  int v0 = f[0], v1 = f[1], v2 = f[2];
  float* s = &g_samp[b][3 * i];
  #pragma unroll
  for (int d = 0; d < 3; d++)
    s[d] = w0 * pr[3 * v0 + d] + w1 * pr[3 * v1 + d] + w2 * pr[3 * v2 + d];
}

// ---------------- chamfer: gt -> pred_all (min only) ----------------
__global__ void k_d1(Params P) {
  int b = blockIdx.z;
  int Vb = vb_of(b), Mb = Vb + NSAMP;
  int gi = blockIdx.x * blockDim.x + threadIdx.x;
  bool act = gi < NGT;
  float gx = 0, gy = 0, gz = 0, gg = 0;
  if (act) {
    gx = P.gt[3 * gi]; gy = P.gt[3 * gi + 1]; gz = P.gt[3 * gi + 2];
    gg = gx * gx + gy * gy + gz * gz;
  }
  float best = 3.4e38f;
  __shared__ float4 tile[TILE];
  const float* pr = P.pred[b];
  const float* sp = g_samp[b];
  for (int base = 0; base < Mb; base += TILE) {
    for (int t = threadIdx.x; t < TILE; t += blockDim.x) {
      int j = base + t;
      float4 q;
      if (j < Mb) {
        const float* src = (j < Vb) ? (pr + 3 * j) : (sp + 3 * (j - Vb));
        q.x = src[0]; q.y = src[1]; q.z = src[2];
        q.w = q.x * q.x + q.y * q.y + q.z * q.z;
      } else { q.x = 0.f; q.y = 0.f; q.z = 0.f; q.w = 3.4e38f; }
      tile[t] = q;
    }
    __syncthreads();
    #pragma unroll 8
    for (int t = 0; t < TILE; t++) {
      float4 q = tile[t];
      float d = gg + q.w - 2.0f * (gx * q.x + gy * q.y + gz * q.z);
      best = fminf(best, d);
    }
    __syncthreads();
  }
  block_add(act ? (double)best * (3000.0 / NGT) : 0.0);
}

// ---------------- chamfer: pred_all -> gt (min + first-argmin) ----------------
__global__ void k_d2(Params P) {
  int b = blockIdx.z;
  int Vb = vb_of(b), Mb = Vb + NSAMP;
  int j = blockIdx.x * blockDim.x + threadIdx.x;
  bool act = j < Mb;
  float px = 0, py = 0, pz = 0, pp = 0;
  if (act) {
    const float* src = (j < Vb) ? (P.pred[b] + 3 * j) : (g_samp[b] + 3 * (j - Vb));
    px = src[0]; py = src[1]; pz = src[2];
    pp = px * px + py * py + pz * pz;
  }
  float best = 3.4e38f; int bi = 0;
  __shared__ float4 tile[TILE];
  for (int base = 0; base < NGT; base += TILE) {
    for (int t = threadIdx.x; t < TILE; t += blockDim.x) {
      int k = base + t;
      float4 q;
      if (k < NGT) {
        q.x = P.gt[3 * k]; q.y = P.gt[3 * k + 1]; q.z = P.gt[3 * k + 2];
        q.w = q.x * q.x + q.y * q.y + q.z * q.z;
      } else { q.x = 0.f; q.y = 0.f; q.z = 0.f; q.w = 3.4e38f; }
      tile[t] = q;
    }
    __syncthreads();
    #pragma unroll 4
    for (int t = 0; t < TILE; t++) {
      float4 q = tile[t];
      float d = pp + q.w - 2.0f * (px * q.x + py * q.y + pz * q.z);
      if (d < best) { best = d; bi = base + t; }   // strict < => first argmin (matches jnp)
    }
    __syncthreads();
  }
  if (act && j < Vb) g_imin[b][j] = bi;
  block_add(act ? (double)best * (3000.0 * 0.55 / Mb) : 0.0);
}

// ---------------- edge + normal losses ----------------
__global__ void k_edge(Params P) {
  int b = blockIdx.z;
  int Vb = vb_of(b), E = 3 * Vb;
  int i = blockIdx.x * blockDim.x + threadIdx.x;
  double v = 0.0;
  if (i < E) {
    const int* eg = P.edges[b];
    int e0 = eg[2 * i], e1 = eg[2 * i + 1];
    const float* pr = P.pred[b];
    float dx = pr[3 * e0]     - pr[3 * e1];
    float dy = pr[3 * e0 + 1] - pr[3 * e1 + 1];
    float dz = pr[3 * e0 + 2] - pr[3 * e1 + 2];
    float esq = dx * dx + dy * dy + dz * dz;
    float inv = 1.0f / fmaxf(sqrtf(esq), 1e-12f);
    int gi = g_imin[b][e0];
    const float* nn = P.gtn + 3 * gi;
    float nx = nn[0], ny = nn[1], nz = nn[2];
    float ninv = 1.0f / fmaxf(sqrtf(nx * nx + ny * ny + nz * nz), 1e-12f);
    float dot = (dx * nx + dy * ny + dz * nz) * inv * ninv;
    // W_EDGE * edge = 359 * sum/(3V);  W_NORM * normal = 0.5 * sum|dot|/(3V)
    v = (359.0 / E) * (double)esq + (0.5 / E) * (double)fabsf(dot);
  }
  block_add(v);
}

// ---------------- laplacian + move losses ----------------
__global__ void k_lap(Params P) {
  int b = blockIdx.z;
  int Vb = vb_of(b);
  float lapc = (b == 0) ? 0.2f : 1.0f;
  int i = blockIdx.x * blockDim.x + threadIdx.x;
  double v = 0.0;
  if (i < Vb) {
    const int* row = P.lap[b] + 10 * i;
    float cnt = (float)row[9];
    const float* pr = P.pred[b];
    const float* bf = P.bef[b];
    float spx = 0, spy = 0, spz = 0, sbx = 0, sby = 0, sbz = 0;
    #pragma unroll
    for (int k = 0; k < 8; k++) {
      int n = row[k];
      if (n >= 0) {
        spx += pr[3 * n]; spy += pr[3 * n + 1]; spz += pr[3 * n + 2];
        sbx += bf[3 * n]; sby += bf[3 * n + 1]; sbz += bf[3 * n + 2];
      }
    }
    float lbx = bf[3 * i]     - sbx / cnt;
    float lby = bf[3 * i + 1] - sby / cnt;
    float lbz = bf[3 * i + 2] - sbz / cnt;
    float lpx = pr[3 * i]     - spx / cnt;
    float lpy = pr[3 * i + 1] - spy / cnt;
    float lpz = pr[3 * i + 2] - spz / cnt;
    float d0 = lbx - lpx, d1 = lby - lpy, d2 = lbz - lpz;
    float lapsq = d0 * d0 + d1 * d1 + d2 * d2;
    float m0 = bf[3 * i] - pr[3 * i];
    float m1 = bf[3 * i + 1] - pr[3 * i + 1];
    float m2 = bf[3 * i + 2] - pr[3 * i + 2];
    float movesq = m0 * m0 + m1 * m1 + m2 * m2;
    // W_LAP * lap_c * sum/V  +  (b>0) W_MOVE * lap_c * sum/V
    v = (1500.0 * (double)lapc / Vb) * (double)lapsq;
    if (b > 0) v += (50.0 * (double)lapc / Vb) * (double)movesq;
  }
  block_add(v);
}

__global__ void k_final(Params P) { P.out[0] = (float)g_loss; }

// ---------------- launch ----------------
extern "C" void kernel_launch(void* const* d_in, const int* in_sizes, int n_in,
                              void* d_out, int out_size) {
  (void)in_sizes; (void)n_in; (void)out_size;
  Params p;
  p.gt  = (const float*)d_in[0];
  p.gtn = (const float*)d_in[1];
  for (int i = 0; i < 3; i++) {
    p.pred[i]  = (const float*)d_in[2 + 5 * i];
    p.bef[i]   = (const float*)d_in[3 + 5 * i];
    p.edges[i] = (const int*)  d_in[4 + 5 * i];
    p.faces[i] = (const int*)  d_in[5 + 5 * i];
    p.lap[i]   = (const int*)  d_in[6 + 5 * i];
  }
  p.out = (float*)d_out;

  dim3 bs(128);
  k_init  <<<1, 1>>>();
  k_sample<<<dim3(32, 1, 3),  bs>>>(p);   // 4000 samples per mesh block
  k_d1    <<<dim3(63, 1, 3),  bs>>>(p);   // 8000 gt points
  k_d2    <<<dim3(112, 1, 3), bs>>>(p);   // up to 14242 pred points
  k_edge  <<<dim3(241, 1, 3), bs>>>(p);   // up to 30726 edges
  k_lap   <<<dim3(81, 1, 3),  bs>>>(p);   // up to 10242 vertices
  k_final <<<1, 1>>>(p);
}

// round 2
// speedup vs baseline: 2.6003x; 2.6003x over previous
#include <cuda_runtime.h>

#define NGT   8000
#define NSAMP 4000
#define TILE  128
#define MAXV  10242
#define MAXM  (MAXV + NSAMP)
#define SEGS  6

static __device__ double g_loss;
static __device__ float  g_samp[3][NSAMP * 3];
static __device__ int    g_imin[3][MAXV];
static __device__ unsigned           g_best1[3][NGT];    // encoded max-score, gt->pred
static __device__ unsigned long long g_best2[3][MAXM];   // (enc(score)<<32)|~idx, pred->gt

struct Params {
  const float* gt;  const float* gtn;
  const float* pred[3]; const float* bef[3];
  const int*   edges[3]; const int* faces[3]; const int* lap[3];
  float* out;
};

__device__ __forceinline__ int vb_of(int b) { return b == 0 ? 642 : (b == 1 ? 2562 : 10242); }

// order-preserving float <-> uint (monotone increasing)
__device__ __forceinline__ unsigned enc_f(float f) {
  unsigned u = __float_as_uint(f);
  return (u & 0x80000000u) ? ~u : (u | 0x80000000u);
}
__device__ __forceinline__ float dec_f(unsigned u) {
  unsigned b = (u & 0x80000000u) ? (u ^ 0x80000000u) : ~u;
  return __uint_as_float(b);
}

// ---------------- threefry2x32 (exact JAX block) ----------------
__device__ __forceinline__ void tf(unsigned k0, unsigned k1,
                                   unsigned x0, unsigned x1,
                                   unsigned& o0, unsigned& o1) {
  unsigned ks2 = k0 ^ k1 ^ 0x1BD11BDAu;
  x0 += k0; x1 += k1;
#define R_(r) { x0 += x1; x1 = (x1 << (r)) | (x1 >> (32 - (r))); x1 ^= x0; }
  R_(13) R_(15) R_(26) R_(6)  x0 += k1;  x1 += ks2 + 1u;
  R_(17) R_(29) R_(16) R_(24) x0 += ks2; x1 += k0  + 2u;
  R_(13) R_(15) R_(26) R_(6)  x0 += k0;  x1 += k1  + 3u;
  R_(17) R_(29) R_(16) R_(24) x0 += k1;  x1 += ks2 + 4u;
  R_(13) R_(15) R_(26) R_(6)  x0 += ks2; x1 += k0  + 5u;
#undef R_
  o0 = x0; o1 = x1;
}

// block-level sum -> one double atomic (blockDim.x == 128)
__device__ __forceinline__ void block_add(double v) {
  #pragma unroll
  for (int o = 16; o; o >>= 1) v += __shfl_down_sync(0xffffffffu, v, o);
  __shared__ double ws[4];
  int lane = threadIdx.x & 31, w = threadIdx.x >> 5;
  if (lane == 0) ws[w] = v;
  __syncthreads();
  if (w == 0) {
    double t = (lane < 4) ? ws[lane] : 0.0;
    t += __shfl_down_sync(0xffffffffu, t, 2);
    t += __shfl_down_sync(0xffffffffu, t, 1);
    if (lane == 0) atomicAdd(&g_loss, t);
  }
}

// ---------------- reset ----------------
__global__ void k_reset() {
  int i = blockIdx.x * blockDim.x + threadIdx.x;
  if (i == 0) g_loss = 0.0;
  for (int j = i; j < 3 * NGT; j += gridDim.x * blockDim.x)
    (&g_best1[0][0])[j] = 0u;
  for (int j = i; j < 3 * MAXM; j += gridDim.x * blockDim.x)
    (&g_best2[0][0])[j] = 0ull;
}

// ---------------- triangle sampling with exact JAX PRNG ----------------
__global__ void k_sample(Params P) {
  int b = blockIdx.z;
  int i = blockIdx.x * blockDim.x + threadIdx.x;
  if (i >= NSAMP) return;
  int Vb = vb_of(b);
  unsigned span = 2u * (unsigned)Vb;

  unsigned kb0, kb1; tf(0u, 42u, 0u, (unsigned)b, kb0, kb1);
  unsigned hi, lo, u0b, u1b;
  unsigned kf0, kf1, ku0, ku1, k10, k11, k20, k21, t0, t1;
  tf(kb0, kb1, 0u, 0u, kf0, kf1);
  tf(kb0, kb1, 0u, 1u, ku0, ku1);
  tf(kf0, kf1, 0u, 0u, k10, k11);
  tf(kf0, kf1, 0u, 1u, k20, k21);
  tf(k10, k11, 0u, (unsigned)i, t0, t1);            hi  = t0 ^ t1;
  tf(k20, k21, 0u, (unsigned)i, t0, t1);            lo  = t0 ^ t1;
  tf(ku0, ku1, 0u, (unsigned)(2 * i),     t0, t1);  u0b = t0 ^ t1;
  tf(ku0, ku1, 0u, (unsigned)(2 * i + 1), t0, t1);  u1b = t0 ^ t1;

  unsigned m = 65536u % span; m = (m * m) % span;
  unsigned off = ((hi % span) * m + (lo % span)) % span;
  int fidx = (int)off;
  float u0 = __uint_as_float((u0b >> 9) | 0x3F800000u) - 1.0f;
  float u1 = __uint_as_float((u1b >> 9) | 0x3F800000u) - 1.0f;
  float r1 = sqrtf(u0);
  float w0 = 1.0f - r1, w1 = r1 * (1.0f - u1), w2 = r1 * u1;

  const int* f = P.faces[b] + 3 * fidx;
  const float* pr = P.pred[b];
  int v0 = f[0], v1 = f[1], v2 = f[2];
  float* s = &g_samp[b][3 * i];
  #pragma unroll
  for (int d = 0; d < 3; d++)
    s[d] = w0 * pr[3 * v0 + d] + w1 * pr[3 * v1 + d] + w2 * pr[3 * v2 + d];
}

// ---------------- chamfer d1: gt -> pred_all (max score, split-K) ----------------
// score = dot(g,q) - 0.5|q|^2 ; min d = |g|^2 - 2*max score
__global__ void k_d1(Params P) {
  int b = blockIdx.z;
  int Vb = vb_of(b), Mb = Vb + NSAMP;
  int base_pt = blockIdx.x * 512;             // 4 pts/thread * 128 threads
  int tid = threadIdx.x;

  float x[4], y[4], z[4], bs[4];
  #pragma unroll
  for (int k = 0; k < 4; k++) {
    int gi = base_pt + k * 128 + tid;
    bool a = gi < NGT;
    int s = a ? gi : 0;
    x[k] = P.gt[3 * s]; y[k] = P.gt[3 * s + 1]; z[k] = P.gt[3 * s + 2];
    bs[k] = -3.4e38f;
  }

  int segLen = (Mb + SEGS - 1) / SEGS;
  int segLo = blockIdx.y * segLen;
  int segHi = min(segLo + segLen, Mb);

  __shared__ float4 tile[TILE];
  const float* pr = P.pred[b];
  const float* sp = g_samp[b];

  for (int tb = segLo; tb < segHi; tb += TILE) {
    {
      int j = tb + tid;
      float4 q;
      if (j < segHi) {
        const float* src = (j < Vb) ? (pr + 3 * j) : (sp + 3 * (j - Vb));
        q.x = src[0]; q.y = src[1]; q.z = src[2];
        q.w = 0.5f * (q.x * q.x + q.y * q.y + q.z * q.z);
      } else { q.x = 0.f; q.y = 0.f; q.z = 0.f; q.w = 3.4e38f; }
      tile[tid] = q;
    }
    __syncthreads();
    int lim = min(TILE, segHi - tb);
    #pragma unroll 8
    for (int t = 0; t < lim; t++) {
      float4 q = tile[t];
      #pragma unroll
      for (int k = 0; k < 4; k++) {
        float s = fmaf(x[k], q.x, fmaf(y[k], q.y, fmaf(z[k], q.z, -q.w)));
        bs[k] = fmaxf(bs[k], s);
      }
    }
    __syncthreads();
  }
  #pragma unroll
  for (int k = 0; k < 4; k++) {
    int gi = base_pt + k * 128 + tid;
    if (gi < NGT) atomicMax(&g_best1[b][gi], enc_f(bs[k]));
  }
}

// ---------------- chamfer d2: pred_all -> gt (max score + first argmax, split-K) ----------------
__global__ void k_d2(Params P) {
  int b = blockIdx.z;
  int Vb = vb_of(b), Mb = Vb + NSAMP;
  int base_pt = blockIdx.x * 512;
  if (base_pt >= Mb) return;
  int tid = threadIdx.x;

  float x[4], y[4], z[4], bs[4]; int bi[4];
  #pragma unroll
  for (int k = 0; k < 4; k++) {
    int j = base_pt + k * 128 + tid;
    int s = (j < Mb) ? j : 0;
    const float* src = (s < Vb) ? (P.pred[b] + 3 * s) : (g_samp[b] + 3 * (s - Vb));
    x[k] = src[0]; y[k] = src[1]; z[k] = src[2];
    bs[k] = -3.4e38f; bi[k] = 0;
  }

  int segLen = (NGT + SEGS - 1) / SEGS;
  int segLo = blockIdx.y * segLen;
  int segHi = min(segLo + segLen, NGT);

  __shared__ float4 tile[TILE];
  for (int tb = segLo; tb < segHi; tb += TILE) {
    {
      int j = tb + tid;
      float4 q;
      if (j < segHi) {
        q.x = P.gt[3 * j]; q.y = P.gt[3 * j + 1]; q.z = P.gt[3 * j + 2];
        q.w = 0.5f * (q.x * q.x + q.y * q.y + q.z * q.z);
      } else { q.x = 0.f; q.y = 0.f; q.z = 0.f; q.w = 3.4e38f; }
      tile[tid] = q;
    }
    __syncthreads();
    int lim = min(TILE, segHi - tb);
    #pragma unroll 8
    for (int t = 0; t < lim; t++) {
      float4 q = tile[t];
      #pragma unroll
      for (int k = 0; k < 4; k++) {
        float s = fmaf(x[k], q.x, fmaf(y[k], q.y, fmaf(z[k], q.z, -q.w)));
        if (s > bs[k]) { bs[k] = s; bi[k] = tb + t; }   // strict > => first argmax
      }
    }
    __syncthreads();
  }
  #pragma unroll
  for (int k = 0; k < 4; k++) {
    int j = base_pt + k * 128 + tid;
    if (j < Mb) {
      unsigned long long key =
          ((unsigned long long)enc_f(bs[k]) << 32) | (unsigned)(~bi[k]);
      atomicMax(&g_best2[b][j], key);
    }
  }
}

// ---------------- combine mins -> chamfer sums + argmin indices ----------------
__global__ void k_reduce(Params P) {
  int b = blockIdx.z;
  int Vb = vb_of(b), Mb = Vb + NSAMP;
  int i = blockIdx.x * blockDim.x + threadIdx.x;
  double v = 0.0;
  if (i < NGT) {
    float gx = P.gt[3 * i], gy = P.gt[3 * i + 1], gz = P.gt[3 * i + 2];
    float gg = gx * gx + gy * gy + gz * gz;
    float d = gg - 2.0f * dec_f(g_best1[b][i]);
    v += (3000.0 / NGT) * (double)d;
  }
  if (i < Mb) {
    const float* src = (i < Vb) ? (P.pred[b] + 3 * i) : (g_samp[b] + 3 * (i - Vb));
    float px = src[0], py = src[1], pz = src[2];
    float pp = px * px + py * py + pz * pz;
    unsigned long long key = g_best2[b][i];
    float d = pp - 2.0f * dec_f((unsigned)(key >> 32));
    int idx = (int)(~(unsigned)key);
    v += (3000.0 * 0.55 / Mb) * (double)d;
    if (i < Vb) g_imin[b][i] = idx;
  }
  block_add(v);
}

// ---------------- edge + normal losses ----------------
__global__ void k_edge(Params P) {
  int b = blockIdx.z;
  int Vb = vb_of(b), E = 3 * Vb;
  int i = blockIdx.x * blockDim.x + threadIdx.x;
  double v = 0.0;
  if (i < E) {
    const int* eg = P.edges[b];
    int e0 = eg[2 * i], e1 = eg[2 * i + 1];
    const float* pr = P.pred[b];
    float dx = pr[3 * e0]     - pr[3 * e1];
    float dy = pr[3 * e0 + 1] - pr[3 * e1 + 1];
    float dz = pr[3 * e0 + 2] - pr[3 * e1 + 2];
    float esq = dx * dx + dy * dy + dz * dz;
    float inv = 1.0f / fmaxf(sqrtf(esq), 1e-12f);
    int gi = g_imin[b][e0];
    const float* nn = P.gtn + 3 * gi;
    float nx = nn[0], ny = nn[1], nz = nn[2];
    float ninv = 1.0f / fmaxf(sqrtf(nx * nx + ny * ny + nz * nz), 1e-12f);
    float dot = (dx * nx + dy * ny + dz * nz) * inv * ninv;
    v = (359.0 / E) * (double)esq + (0.5 / E) * (double)fabsf(dot);
  }
  block_add(v);
}

// ---------------- laplacian + move losses ----------------
__global__ void k_lap(Params P) {
  int b = blockIdx.z;
  int Vb = vb_of(b);
  float lapc = (b == 0) ? 0.2f : 1.0f;
  int i = blockIdx.x * blockDim.x + threadIdx.x;
  double v = 0.0;
  if (i < Vb) {
    const int* row = P.lap[b] + 10 * i;
    float cnt = (float)row[9];
    const float* pr = P.pred[b];
    const float* bf = P.bef[b];
    float spx = 0, spy = 0, spz = 0, sbx = 0, sby = 0, sbz = 0;
    #pragma unroll
    for (int k = 0; k < 8; k++) {
      int n = row[k];
      if (n >= 0) {
        spx += pr[3 * n]; spy += pr[3 * n + 1]; spz += pr[3 * n + 2];
        sbx += bf[3 * n]; sby += bf[3 * n + 1]; sbz += bf[3 * n + 2];
      }
    }
    float lbx = bf[3 * i]     - sbx / cnt;
    float lby = bf[3 * i + 1] - sby / cnt;
    float lbz = bf[3 * i + 2] - sbz / cnt;
    float lpx = pr[3 * i]     - spx / cnt;
    float lpy = pr[3 * i + 1] - spy / cnt;
    float lpz = pr[3 * i + 2] - spz / cnt;
    float d0 = lbx - lpx, d1 = lby - lpy, d2 = lbz - lpz;
    float lapsq = d0 * d0 + d1 * d1 + d2 * d2;
    float m0 = bf[3 * i] - pr[3 * i];
    float m1 = bf[3 * i + 1] - pr[3 * i + 1];
    float m2 = bf[3 * i + 2] - pr[3 * i + 2];
    float movesq = m0 * m0 + m1 * m1 + m2 * m2;
    v = (1500.0 * (double)lapc / Vb) * (double)lapsq;
    if (b > 0) v += (50.0 * (double)lapc / Vb) * (double)movesq;
  }
  block_add(v);
}

__global__ void k_final(Params P) { P.out[0] = (float)g_loss; }

// ---------------- launch ----------------
extern "C" void kernel_launch(void* const* d_in, const int* in_sizes, int n_in,
                              void* d_out, int out_size) {
  (void)in_sizes; (void)n_in; (void)out_size;
  Params p;
  p.gt  = (const float*)d_in[0];
  p.gtn = (const float*)d_in[1];
  for (int i = 0; i < 3; i++) {
    p.pred[i]  = (const float*)d_in[2 + 5 * i];
    p.bef[i]   = (const float*)d_in[3 + 5 * i];
    p.edges[i] = (const int*)  d_in[4 + 5 * i];
    p.faces[i] = (const int*)  d_in[5 + 5 * i];
    p.lap[i]   = (const int*)  d_in[6 + 5 * i];
  }
  p.out = (float*)d_out;

  dim3 bs(128);
  k_reset <<<dim3(96), 256>>>();
  k_sample<<<dim3(32, 1, 3),        bs>>>(p);
  k_d1    <<<dim3(16, SEGS, 3),     bs>>>(p);   // 8000 gt pts, 4/thread, split-K
  k_d2    <<<dim3(28, SEGS, 3),     bs>>>(p);   // up to 14242 pred pts, 4/thread, split-K
  k_reduce<<<dim3(112, 1, 3),       bs>>>(p);
  k_edge  <<<dim3(241, 1, 3),       bs>>>(p);
  k_lap   <<<dim3(81, 1, 3),        bs>>>(p);
  k_final <<<1, 1>>>(p);
}

// round 3
// speedup vs baseline: 2.6322x; 1.0123x over previous
#include <cuda_runtime.h>

#define NGT   8000
#define NSAMP 4000
#define TILE  128
#define MAXV  10242
#define MAXM  (MAXV + NSAMP)
#define SEGS  16
#define NPT   8
typedef unsigned long long ull;

static __device__ double g_loss;
static __device__ float  g_samp[3][NSAMP * 3];
static __device__ int    g_imin[3][MAXV];
static __device__ unsigned g_best1[3][NGT];          // encoded max-score, gt->pred
static __device__ float    g_d2seg[3][SEGS][MAXM];   // per-segment max score, pred->gt

struct Params {
  const float* gt;  const float* gtn;
  const float* pred[3]; const float* bef[3];
  const int*   edges[3]; const int* faces[3]; const int* lap[3];
  float* out;
};

__device__ __forceinline__ int vb_of(int b) { return b == 0 ? 642 : (b == 1 ? 2562 : 10242); }

// order-preserving float <-> uint (monotone increasing)
__device__ __forceinline__ unsigned enc_f(float f) {
  unsigned u = __float_as_uint(f);
  return (u & 0x80000000u) ? ~u : (u | 0x80000000u);
}
__device__ __forceinline__ float dec_f(unsigned u) {
  unsigned b = (u & 0x80000000u) ? (u ^ 0x80000000u) : ~u;
  return __uint_as_float(b);
}

// ---- packed f32x2 helpers ----
__device__ __forceinline__ ull ffma2(ull a, ull b, ull c) {
  ull d;
  asm("fma.rn.f32x2 %0, %1, %2, %3;" : "=l"(d) : "l"(a), "l"(b), "l"(c));
  return d;
}
__device__ __forceinline__ ull dup2(float v) {
  ull r; unsigned u = __float_as_uint(v);
  asm("mov.b64 %0, {%1, %1};" : "=l"(r) : "r"(u));
  return r;
}
__device__ __forceinline__ void unpk(ull v, float& lo, float& hi) {
  unsigned l, h;
  asm("mov.b64 {%0, %1}, %2;" : "=r"(l), "=r"(h) : "l"(v));
  lo = __uint_as_float(l); hi = __uint_as_float(h);
}

// pinned-rounding score pieces (must be bit-identical in hot loop & rescan)
__device__ __forceinline__ float wneg_of(float qx, float qy, float qz) {
  return -0.5f * __fmaf_rn(qx, qx, __fmaf_rn(qy, qy, __fmul_rn(qz, qz)));
}
__device__ __forceinline__ float score_of(float x, float y, float z,
                                          float qx, float qy, float qz, float w) {
  return __fmaf_rn(x, qx, __fmaf_rn(y, qy, __fmaf_rn(z, qz, w)));
}

// ---------------- threefry2x32 (exact JAX block) ----------------
__device__ __forceinline__ void tf(unsigned k0, unsigned k1,
                                   unsigned x0, unsigned x1,
                                   unsigned& o0, unsigned& o1) {
  unsigned ks2 = k0 ^ k1 ^ 0x1BD11BDAu;
  x0 += k0; x1 += k1;
#define R_(r) { x0 += x1; x1 = (x1 << (r)) | (x1 >> (32 - (r))); x1 ^= x0; }
  R_(13) R_(15) R_(26) R_(6)  x0 += k1;  x1 += ks2 + 1u;
  R_(17) R_(29) R_(16) R_(24) x0 += ks2; x1 += k0  + 2u;
  R_(13) R_(15) R_(26) R_(6)  x0 += k0;  x1 += k1  + 3u;
  R_(17) R_(29) R_(16) R_(24) x0 += k1;  x1 += ks2 + 4u;
  R_(13) R_(15) R_(26) R_(6)  x0 += ks2; x1 += k0  + 5u;
#undef R_
  o0 = x0; o1 = x1;
}

__device__ __forceinline__ void block_add(double v) {
  #pragma unroll
  for (int o = 16; o; o >>= 1) v += __shfl_down_sync(0xffffffffu, v, o);
  __shared__ double ws[4];
  int lane = threadIdx.x & 31, w = threadIdx.x >> 5;
  if (lane == 0) ws[w] = v;
  __syncthreads();
  if (w == 0) {
    double t = (lane < 4) ? ws[lane] : 0.0;
    t += __shfl_down_sync(0xffffffffu, t, 2);
    t += __shfl_down_sync(0xffffffffu, t, 1);
    if (lane == 0) atomicAdd(&g_loss, t);
  }
}

__global__ void k_reset() {
  int i = blockIdx.x * blockDim.x + threadIdx.x;
  if (i == 0) g_loss = 0.0;
  for (int j = i; j < 3 * NGT; j += gridDim.x * blockDim.x)
    (&g_best1[0][0])[j] = 0u;
}

// ---------------- triangle sampling with exact JAX PRNG ----------------
__global__ void k_sample(Params P) {
  int b = blockIdx.z;
  int i = blockIdx.x * blockDim.x + threadIdx.x;
  if (i >= NSAMP) return;
  int Vb = vb_of(b);
  unsigned span = 2u * (unsigned)Vb;

  unsigned kb0, kb1; tf(0u, 42u, 0u, (unsigned)b, kb0, kb1);
  unsigned hi, lo, u0b, u1b;
  unsigned kf0, kf1, ku0, ku1, k10, k11, k20, k21, t0, t1;
  tf(kb0, kb1, 0u, 0u, kf0, kf1);
  tf(kb0, kb1, 0u, 1u, ku0, ku1);
  tf(kf0, kf1, 0u, 0u, k10, k11);
  tf(kf0, kf1, 0u, 1u, k20, k21);
  tf(k10, k11, 0u, (unsigned)i, t0, t1);            hi  = t0 ^ t1;
  tf(k20, k21, 0u, (unsigned)i, t0, t1);            lo  = t0 ^ t1;
  tf(ku0, ku1, 0u, (unsigned)(2 * i),     t0, t1);  u0b = t0 ^ t1;
  tf(ku0, ku1, 0u, (unsigned)(2 * i + 1), t0, t1);  u1b = t0 ^ t1;

  unsigned m = 65536u % span; m = (m * m) % span;
  unsigned off = ((hi % span) * m + (lo % span)) % span;
  int fidx = (int)off;
  float u0 = __uint_as_float((u0b >> 9) | 0x3F800000u) - 1.0f;
  float u1 = __uint_as_float((u1b >> 9) | 0x3F800000u) - 1.0f;
  float r1 = sqrtf(u0);
  float w0 = 1.0f - r1, w1 = r1 * (1.0f - u1), w2 = r1 * u1;

  const int* f = P.faces[b] + 3 * fidx;
  const float* pr = P.pred[b];
  int v0 = f[0], v1 = f[1], v2 = f[2];
  float* s = &g_samp[b][3 * i];
  #pragma unroll
  for (int d = 0; d < 3; d++)
    s[d] = w0 * pr[3 * v0 + d] + w1 * pr[3 * v1 + d] + w2 * pr[3 * v2 + d];
}

// shared tile: SoA pairs. sxy[h] = {x0,x1,y0,y1}; szw[h] = {z0,z1,w0,w1}
// score = fma(x,qx, fma(y,qy, fma(z,qz, w))), w = -0.5|q|^2 (neutral pad w=-3.4e38)

// ---------------- chamfer d1: gt -> pred_all (max score, split-K) ----------------
__global__ void k_d1(Params P) {
  int b = blockIdx.z;
  int Vb = vb_of(b), Mb = Vb + NSAMP;
  int base_pt = blockIdx.x * (TILE * NPT);
  int tid = threadIdx.x;

  ull xd[NPT], yd[NPT], zd[NPT]; float bs[NPT];
  #pragma unroll
  for (int k = 0; k < NPT; k++) {
    int gi = base_pt + k * TILE + tid;
    int s = (gi < NGT) ? gi : 0;
    xd[k] = dup2(P.gt[3 * s]); yd[k] = dup2(P.gt[3 * s + 1]); zd[k] = dup2(P.gt[3 * s + 2]);
    bs[k] = -3.4e38f;
  }

  int segLen = (Mb + SEGS - 1) / SEGS;
  int segLo = blockIdx.y * segLen;
  int segHi = min(segLo + segLen, Mb);

  __shared__ float4 sxy[TILE / 2], szw[TILE / 2];
  const float* pr = P.pred[b];
  const float* sp = g_samp[b];

  for (int tb = segLo; tb < segHi; tb += TILE) {
    {
      int j = tb + tid;
      float qx = 0.f, qy = 0.f, qz = 0.f, qw = -3.4e38f;
      if (j < segHi) {
        const float* src = (j < Vb) ? (pr + 3 * j) : (sp + 3 * (j - Vb));
        qx = src[0]; qy = src[1]; qz = src[2];
        qw = wneg_of(qx, qy, qz);
      }
      int h = tid >> 1, o = tid & 1;
      ((float*)sxy)[4 * h + o]     = qx;
      ((float*)sxy)[4 * h + 2 + o] = qy;
      ((float*)szw)[4 * h + o]     = qz;
      ((float*)szw)[4 * h + 2 + o] = qw;
    }
    __syncthreads();
    #pragma unroll 4
    for (int t2 = 0; t2 < TILE / 2; t2++) {
      ull x01 = ((const ull*)sxy)[2 * t2], y01 = ((const ull*)sxy)[2 * t2 + 1];
      ull z01 = ((const ull*)szw)[2 * t2], w01 = ((const ull*)szw)[2 * t2 + 1];
      #pragma unroll
      for (int k = 0; k < NPT; k++) {
        ull s2 = ffma2(xd[k], x01, ffma2(yd[k], y01, ffma2(zd[k], z01, w01)));
        float lo, hi; unpk(s2, lo, hi);
        bs[k] = fmaxf(bs[k], lo);
        bs[k] = fmaxf(bs[k], hi);
      }
    }
    __syncthreads();
  }
  #pragma unroll
  for (int k = 0; k < NPT; k++) {
    int gi = base_pt + k * TILE + tid;
    if (gi < NGT) atomicMax(&g_best1[b][gi], enc_f(bs[k]));
  }
}

// ---------------- chamfer d2: pred_all -> gt (per-segment max, no argmax) ----------------
__global__ void k_d2(Params P) {
  int b = blockIdx.z;
  int Vb = vb_of(b), Mb = Vb + NSAMP;
  int base_pt = blockIdx.x * (TILE * NPT);
  if (base_pt >= Mb) return;
  int tid = threadIdx.x;

  ull xd[NPT], yd[NPT], zd[NPT]; float bs[NPT];
  #pragma unroll
  for (int k = 0; k < NPT; k++) {
    int j = base_pt + k * TILE + tid;
    int s = (j < Mb) ? j : 0;
    const float* src = (s < Vb) ? (P.pred[b] + 3 * s) : (g_samp[b] + 3 * (s - Vb));
    xd[k] = dup2(src[0]); yd[k] = dup2(src[1]); zd[k] = dup2(src[2]);
    bs[k] = -3.4e38f;
  }

  const int segLen = (NGT + SEGS - 1) / SEGS;   // 500
  int segLo = blockIdx.y * segLen;
  int segHi = min(segLo + segLen, NGT);

  __shared__ float4 sxy[TILE / 2], szw[TILE / 2];
  for (int tb = segLo; tb < segHi; tb += TILE) {
    {
      int j = tb + tid;
      float qx = 0.f, qy = 0.f, qz = 0.f, qw = -3.4e38f;
      if (j < segHi) {
        qx = P.gt[3 * j]; qy = P.gt[3 * j + 1]; qz = P.gt[3 * j + 2];
        qw = wneg_of(qx, qy, qz);
      }
      int h = tid >> 1, o = tid & 1;
      ((float*)sxy)[4 * h + o]     = qx;
      ((float*)sxy)[4 * h + 2 + o] = qy;
      ((float*)szw)[4 * h + o]     = qz;
      ((float*)szw)[4 * h + 2 + o] = qw;
    }
    __syncthreads();
    #pragma unroll 4
    for (int t2 = 0; t2 < TILE / 2; t2++) {
      ull x01 = ((const ull*)sxy)[2 * t2], y01 = ((const ull*)sxy)[2 * t2 + 1];
      ull z01 = ((const ull*)szw)[2 * t2], w01 = ((const ull*)szw)[2 * t2 + 1];
      #pragma unroll
      for (int k = 0; k < NPT; k++) {
        ull s2 = ffma2(xd[k], x01, ffma2(yd[k], y01, ffma2(zd[k], z01, w01)));
        float lo, hi; unpk(s2, lo, hi);
        bs[k] = fmaxf(bs[k], lo);
        bs[k] = fmaxf(bs[k], hi);
      }
    }
    __syncthreads();
  }
  #pragma unroll
  for (int k = 0; k < NPT; k++) {
    int j = base_pt + k * TILE + tid;
    if (j < Mb) g_d2seg[b][blockIdx.y][j] = bs[k];
  }
}

// ---------------- rescan: first-argmax index for vertices only ----------------
__global__ void k_rescan(Params P) {
  int b = blockIdx.z;
  int Vb = vb_of(b);
  int i = blockIdx.x * blockDim.x + threadIdx.x;
  if (i >= Vb) return;

  // first segment attaining the global max (strict >)
  float best = -3.4e38f; int bseg = 0;
  #pragma unroll
  for (int s = 0; s < SEGS; s++) {
    float v = g_d2seg[b][s][i];
    if (v > best) { best = v; bseg = s; }
  }
  const int segLen = (NGT + SEGS - 1) / SEGS;
  int lo = bseg * segLen, hi = min(lo + segLen, NGT);

  const float* src = P.pred[b] + 3 * i;   // i < Vb always a vertex
  float x = src[0], y = src[1], z = src[2];
  float bsv = -3.4e38f; int bi = 0;
  for (int j = lo; j < hi; j++) {
    float qx = __ldg(P.gt + 3 * j), qy = __ldg(P.gt + 3 * j + 1), qz = __ldg(P.gt + 3 * j + 2);
    float w = wneg_of(qx, qy, qz);
    float s = score_of(x, y, z, qx, qy, qz, w);
    if (s > bsv) { bsv = s; bi = j; }      // strict > => first argmax
  }
  g_imin[b][i] = bi;
}

// ---------------- combine mins -> chamfer sums ----------------
__global__ void k_reduce(Params P) {
  int b = blockIdx.z;
  int Vb = vb_of(b), Mb = Vb + NSAMP;
  int i = blockIdx.x * blockDim.x + threadIdx.x;
  double v = 0.0;
  if (i < NGT) {
    float gx = P.gt[3 * i], gy = P.gt[3 * i + 1], gz = P.gt[3 * i + 2];
    float gg = gx * gx + gy * gy + gz * gz;
    float d = gg - 2.0f * dec_f(g_best1[b][i]);
    v += (3000.0 / NGT) * (double)d;
  }
  if (i < Mb) {
    const float* src = (i < Vb) ? (P.pred[b] + 3 * i) : (g_samp[b] + 3 * (i - Vb));
    float px = src[0], py = src[1], pz = src[2];
    float pp = px * px + py * py + pz * pz;
    float m = -3.4e38f;
    #pragma unroll
    for (int s = 0; s < SEGS; s++) m = fmaxf(m, g_d2seg[b][s][i]);
    float d = pp - 2.0f * m;
    v += (3000.0 * 0.55 / Mb) * (double)d;
  }
  block_add(v);
}

// ---------------- edge + normal losses ----------------
__global__ void k_edge(Params P) {
  int b = blockIdx.z;
  int Vb = vb_of(b), E = 3 * Vb;
  int i = blockIdx.x * blockDim.x + threadIdx.x;
  double v = 0.0;
  if (i < E) {
    const int* eg = P.edges[b];
    int e0 = eg[2 * i], e1 = eg[2 * i + 1];
    const float* pr = P.pred[b];
    float dx = pr[3 * e0]     - pr[3 * e1];
    float dy = pr[3 * e0 + 1] - pr[3 * e1 + 1];
    float dz = pr[3 * e0 + 2] - pr[3 * e1 + 2];
    float esq = dx * dx + dy * dy + dz * dz;
    float inv = 1.0f / fmaxf(sqrtf(esq), 1e-12f);
    int gi = g_imin[b][e0];
    const float* nn = P.gtn + 3 * gi;
    float nx = nn[0], ny = nn[1], nz = nn[2];
    float ninv = 1.0f / fmaxf(sqrtf(nx * nx + ny * ny + nz * nz), 1e-12f);
    float dot = (dx * nx + dy * ny + dz * nz) * inv * ninv;
    v = (359.0 / E) * (double)esq + (0.5 / E) * (double)fabsf(dot);
  }
  block_add(v);
}

// ---------------- laplacian + move losses ----------------
__global__ void k_lap(Params P) {
  int b = blockIdx.z;
  int Vb = vb_of(b);
  float lapc = (b == 0) ? 0.2f : 1.0f;
  int i = blockIdx.x * blockDim.x + threadIdx.x;
  double v = 0.0;
  if (i < Vb) {
    const int* row = P.lap[b] + 10 * i;
    float cnt = (float)row[9];
    const float* pr = P.pred[b];
    const float* bf = P.bef[b];
    float spx = 0, spy = 0, spz = 0, sbx = 0, sby = 0, sbz = 0;
    #pragma unroll
    for (int k = 0; k < 8; k++) {
      int n = row[k];
      if (n >= 0) {
        spx += pr[3 * n]; spy += pr[3 * n + 1]; spz += pr[3 * n + 2];
        sbx += bf[3 * n]; sby += bf[3 * n + 1]; sbz += bf[3 * n + 2];
      }
    }
    float lbx = bf[3 * i]     - sbx / cnt;
    float lby = bf[3 * i + 1] - sby / cnt;
    float lbz = bf[3 * i + 2] - sbz / cnt;
    float lpx = pr[3 * i]     - spx / cnt;
    float lpy = pr[3 * i + 1] - spy / cnt;
    float lpz = pr[3 * i + 2] - spz / cnt;
    float d0 = lbx - lpx, d1 = lby - lpy, d2 = lbz - lpz;
    float lapsq = d0 * d0 + d1 * d1 + d2 * d2;
    float m0 = bf[3 * i] - pr[3 * i];
    float m1 = bf[3 * i + 1] - pr[3 * i + 1];
    float m2 = bf[3 * i + 2] - pr[3 * i + 2];
    float movesq = m0 * m0 + m1 * m1 + m2 * m2;
    v = (1500.0 * (double)lapc / Vb) * (double)lapsq;
    if (b > 0) v += (50.0 * (double)lapc / Vb) * (double)movesq;
  }
  block_add(v);
}

__global__ void k_final(Params P) { P.out[0] = (float)g_loss; }

// ---------------- launch ----------------
extern "C" void kernel_launch(void* const* d_in, const int* in_sizes, int n_in,
                              void* d_out, int out_size) {
  (void)in_sizes; (void)n_in; (void)out_size;
  Params p;
  p.gt  = (const float*)d_in[0];
  p.gtn = (const float*)d_in[1];
  for (int i = 0; i < 3; i++) {
    p.pred[i]  = (const float*)d_in[2 + 5 * i];
    p.bef[i]   = (const float*)d_in[3 + 5 * i];
    p.edges[i] = (const int*)  d_in[4 + 5 * i];
    p.faces[i] = (const int*)  d_in[5 + 5 * i];
    p.lap[i]   = (const int*)  d_in[6 + 5 * i];
  }
  p.out = (float*)d_out;

  dim3 bs(128);
  k_reset <<<dim3(48), 256>>>();
  k_sample<<<dim3(32, 1, 3),     bs>>>(p);
  k_d1    <<<dim3(8,  SEGS, 3),  bs>>>(p);   // 8000 gt pts, 8/thread, split-K 16
  k_d2    <<<dim3(14, SEGS, 3),  bs>>>(p);   // up to 14242 pred pts, 8/thread, split-K 16
  k_rescan<<<dim3(81, 1, 3),     bs>>>(p);   // vertices only, winning segment rescan
  k_reduce<<<dim3(112, 1, 3),    bs>>>(p);
  k_edge  <<<dim3(241, 1, 3),    bs>>>(p);
  k_lap   <<<dim3(81, 1, 3),     bs>>>(p);
  k_final <<<1, 1>>>(p);
}

// round 4
// speedup vs baseline: 4.3027x; 1.6346x over previous
#include <cuda_runtime.h>

#define NGT   8000
#define NSAMP 4000
#define TILE  128
#define MAXV  10242
#define MAXM  (MAXV + NSAMP)
#define SEGS  16
#define NPT   4
#define PTSPB (TILE * NPT)   // 512 outer points per block
typedef unsigned long long ull;

static __device__ double g_loss;
static __device__ float  g_samp[3][NSAMP * 3];
static __device__ int    g_imin[3][MAXV];
static __device__ unsigned g_best1[3][NGT];          // encoded max-score, gt->pred
static __device__ float    g_d2seg[3][SEGS][MAXM];   // per-segment max score, pred->gt

struct Params {
  const float* gt;  const float* gtn;
  const float* pred[3]; const float* bef[3];
  const int*   edges[3]; const int* faces[3]; const int* lap[3];
  float* out;
};

__device__ __forceinline__ int vb_of(int b) { return b == 0 ? 642 : (b == 1 ? 2562 : 10242); }

__device__ __forceinline__ unsigned enc_f(float f) {
  unsigned u = __float_as_uint(f);
  return (u & 0x80000000u) ? ~u : (u | 0x80000000u);
}
__device__ __forceinline__ float dec_f(unsigned u) {
  unsigned b = (u & 0x80000000u) ? (u ^ 0x80000000u) : ~u;
  return __uint_as_float(b);
}

// ---- packed f32x2 helpers ----
__device__ __forceinline__ ull ffma2(ull a, ull b, ull c) {
  ull d;
  asm("fma.rn.f32x2 %0, %1, %2, %3;" : "=l"(d) : "l"(a), "l"(b), "l"(c));
  return d;
}
__device__ __forceinline__ ull dup2(float v) {
  ull r; unsigned u = __float_as_uint(v);
  asm("mov.b64 %0, {%1, %1};" : "=l"(r) : "r"(u));
  return r;
}
__device__ __forceinline__ void unpk(ull v, float& lo, float& hi) {
  unsigned l, h;
  asm("mov.b64 {%0, %1}, %2;" : "=r"(l), "=r"(h) : "l"(v));
  lo = __uint_as_float(l); hi = __uint_as_float(h);
}

// pinned-rounding score pieces (bit-identical in hot loop & rescan)
__device__ __forceinline__ float wneg_of(float qx, float qy, float qz) {
  return -0.5f * __fmaf_rn(qx, qx, __fmaf_rn(qy, qy, __fmul_rn(qz, qz)));
}
__device__ __forceinline__ float score_of(float x, float y, float z,
                                          float qx, float qy, float qz, float w) {
  return __fmaf_rn(x, qx, __fmaf_rn(y, qy, __fmaf_rn(z, qz, w)));
}

// ---------------- threefry2x32 (exact JAX block) ----------------
__device__ __forceinline__ void tf(unsigned k0, unsigned k1,
                                   unsigned x0, unsigned x1,
                                   unsigned& o0, unsigned& o1) {
  unsigned ks2 = k0 ^ k1 ^ 0x1BD11BDAu;
  x0 += k0; x1 += k1;
#define R_(r) { x0 += x1; x1 = (x1 << (r)) | (x1 >> (32 - (r))); x1 ^= x0; }
  R_(13) R_(15) R_(26) R_(6)  x0 += k1;  x1 += ks2 + 1u;
  R_(17) R_(29) R_(16) R_(24) x0 += ks2; x1 += k0  + 2u;
  R_(13) R_(15) R_(26) R_(6)  x0 += k0;  x1 += k1  + 3u;
  R_(17) R_(29) R_(16) R_(24) x0 += k1;  x1 += ks2 + 4u;
  R_(13) R_(15) R_(26) R_(6)  x0 += ks2; x1 += k0  + 5u;
#undef R_
  o0 = x0; o1 = x1;
}

__device__ __forceinline__ void block_add(double v) {
  #pragma unroll
  for (int o = 16; o; o >>= 1) v += __shfl_down_sync(0xffffffffu, v, o);
  __shared__ double ws[4];
  int lane = threadIdx.x & 31, w = threadIdx.x >> 5;
  if (lane == 0) ws[w] = v;
  __syncthreads();
  if (w == 0) {
    double t = (lane < 4) ? ws[lane] : 0.0;
    t += __shfl_down_sync(0xffffffffu, t, 2);
    t += __shfl_down_sync(0xffffffffu, t, 1);
    if (lane == 0) atomicAdd(&g_loss, t);
  }
}

__global__ void k_reset() {
  int i = blockIdx.x * blockDim.x + threadIdx.x;
  if (i == 0) g_loss = 0.0;
  for (int j = i; j < 3 * NGT; j += gridDim.x * blockDim.x)
    (&g_best1[0][0])[j] = 0u;
}

// ---------------- triangle sampling (exact JAX PRNG) ----------------
__global__ void k_sample(Params P) {
  int b = blockIdx.z;
  int i = blockIdx.x * blockDim.x + threadIdx.x;
  if (i >= NSAMP) return;
  int Vb = vb_of(b);
  unsigned span = 2u * (unsigned)Vb;

  unsigned kb0, kb1; tf(0u, 42u, 0u, (unsigned)b, kb0, kb1);
  unsigned hi, lo, u0b, u1b;
  unsigned kf0, kf1, ku0, ku1, k10, k11, k20, k21, t0, t1;
  tf(kb0, kb1, 0u, 0u, kf0, kf1);
  tf(kb0, kb1, 0u, 1u, ku0, ku1);
  tf(kf0, kf1, 0u, 0u, k10, k11);
  tf(kf0, kf1, 0u, 1u, k20, k21);
  tf(k10, k11, 0u, (unsigned)i, t0, t1);            hi  = t0 ^ t1;
  tf(k20, k21, 0u, (unsigned)i, t0, t1);            lo  = t0 ^ t1;
  tf(ku0, ku1, 0u, (unsigned)(2 * i),     t0, t1);  u0b = t0 ^ t1;
  tf(ku0, ku1, 0u, (unsigned)(2 * i + 1), t0, t1);  u1b = t0 ^ t1;

  unsigned m = 65536u % span; m = (m * m) % span;
  unsigned off = ((hi % span) * m + (lo % span)) % span;
  int fidx = (int)off;
  float u0 = __uint_as_float((u0b >> 9) | 0x3F800000u) - 1.0f;
  float u1 = __uint_as_float((u1b >> 9) | 0x3F800000u) - 1.0f;
  float r1 = sqrtf(u0);
  float w0 = 1.0f - r1, w1 = r1 * (1.0f - u1), w2 = r1 * u1;

  const int* f = P.faces[b] + 3 * fidx;
  const float* pr = P.pred[b];
  int v0 = f[0], v1 = f[1], v2 = f[2];
  float* s = &g_samp[b][3 * i];
  #pragma unroll
  for (int d = 0; d < 3; d++)
    s[d] = w0 * pr[3 * v0 + d] + w1 * pr[3 * v1 + d] + w2 * pr[3 * v2 + d];
}

// ---------------- fused chamfer (both directions, split-K) ----------------
// z in [0,6): b = z%3, dir = z/3.  dir0: outer=gt, inner=pred_all (min only)
//                                  dir1: outer=pred_all, inner=gt (per-seg max)
__global__ void __launch_bounds__(TILE, 8) k_cham(Params P) {
  int z = blockIdx.z;
  int b = (z >= 3) ? z - 3 : z;
  bool d2 = z >= 3;
  int Vb = vb_of(b), Mb = Vb + NSAMP;
  int Nout = d2 ? Mb : NGT;
  int Nin  = d2 ? NGT : Mb;

  int base_pt = blockIdx.x * PTSPB;
  if (base_pt >= Nout) return;
  int tid = threadIdx.x;

  const float* pr = P.pred[b];
  const float* sp = g_samp[b];

  ull xd[NPT], yd[NPT], zd[NPT]; float bsL[NPT], bsH[NPT];
  #pragma unroll
  for (int k = 0; k < NPT; k++) {
    int j = base_pt + k * TILE + tid;
    int s = (j < Nout) ? j : 0;
    const float* src;
    if (d2) src = (s < Vb) ? (pr + 3 * s) : (sp + 3 * (s - Vb));
    else    src = P.gt + 3 * s;
    xd[k] = dup2(src[0]); yd[k] = dup2(src[1]); zd[k] = dup2(src[2]);
    bsL[k] = -3.4e38f; bsH[k] = -3.4e38f;
  }

  int segLen = (Nin + SEGS - 1) / SEGS;
  int segLo = blockIdx.y * segLen;
  int segHi = min(segLo + segLen, Nin);

  __shared__ float4 sxy[TILE / 2], szw[TILE / 2];

  for (int tb = segLo; tb < segHi; tb += TILE) {
    {
      int j = tb + tid;
      float qx = 0.f, qy = 0.f, qz = 0.f, qw = -3.4e38f;
      if (j < segHi) {
        const float* src;
        if (d2) src = P.gt + 3 * j;
        else    src = (j < Vb) ? (pr + 3 * j) : (sp + 3 * (j - Vb));
        qx = src[0]; qy = src[1]; qz = src[2];
        qw = wneg_of(qx, qy, qz);
      }
      int h = tid >> 1, o = tid & 1;
      ((float*)sxy)[4 * h + o]     = qx;
      ((float*)sxy)[4 * h + 2 + o] = qy;
      ((float*)szw)[4 * h + o]     = qz;
      ((float*)szw)[4 * h + 2 + o] = qw;
    }
    __syncthreads();
    #pragma unroll 8
    for (int t2 = 0; t2 < TILE / 2; t2++) {
      ull x01 = ((const ull*)sxy)[2 * t2], y01 = ((const ull*)sxy)[2 * t2 + 1];
      ull z01 = ((const ull*)szw)[2 * t2], w01 = ((const ull*)szw)[2 * t2 + 1];
      #pragma unroll
      for (int k = 0; k < NPT; k++) {
        ull s2 = ffma2(xd[k], x01, ffma2(yd[k], y01, ffma2(zd[k], z01, w01)));
        float lo, hi; unpk(s2, lo, hi);
        bsL[k] = fmaxf(bsL[k], lo);
        bsH[k] = fmaxf(bsH[k], hi);
      }
    }
    __syncthreads();
  }
  #pragma unroll
  for (int k = 0; k < NPT; k++) {
    int j = base_pt + k * TILE + tid;
    float bs = fmaxf(bsL[k], bsH[k]);
    if (j < Nout) {
      if (d2) g_d2seg[b][blockIdx.y][j] = bs;
      else    atomicMax(&g_best1[b][j], enc_f(bs));
    }
  }
}

// ---------------- rescan: warp-per-vertex first-argmax ----------------
__global__ void k_rescan(Params P) {
  int gw = (blockIdx.x * blockDim.x + threadIdx.x) >> 5;  // global warp id
  int lane = threadIdx.x & 31;
  int b, v;
  if (gw < 642)             { b = 0; v = gw; }
  else if (gw < 642 + 2562) { b = 1; v = gw - 642; }
  else if (gw < 13446)      { b = 2; v = gw - 3204; }
  else return;

  // first segment attaining the global max (strict >, segments in order)
  float best = -3.4e38f; int bseg = 0;
  #pragma unroll
  for (int s = 0; s < SEGS; s++) {
    float val = g_d2seg[b][s][v];
    if (val > best) { best = val; bseg = s; }
  }
  const int segLen = (NGT + SEGS - 1) / SEGS;   // 500
  int lo = bseg * segLen, hi = min(lo + segLen, NGT);

  const float* src = P.pred[b] + 3 * v;
  float x = src[0], y = src[1], z = src[2];
  float bsv = -3.4e38f; int bi = 0x7fffffff;
  for (int j = lo + lane; j < hi; j += 32) {
    float qx = __ldg(P.gt + 3 * j), qy = __ldg(P.gt + 3 * j + 1), qz = __ldg(P.gt + 3 * j + 2);
    float w = wneg_of(qx, qy, qz);
    float s = score_of(x, y, z, qx, qy, qz, w);
    if (s > bsv || (s == bsv && j < bi)) { bsv = s; bi = j; }
  }
  #pragma unroll
  for (int o = 16; o; o >>= 1) {
    float so = __shfl_down_sync(0xffffffffu, bsv, o);
    int   io = __shfl_down_sync(0xffffffffu, bi,  o);
    if (so > bsv || (so == bsv && io < bi)) { bsv = so; bi = io; }
  }
  if (lane == 0) g_imin[b][v] = bi;
}

// ---------------- fused tail: reduce / edge+normal / lap+move ----------------
__global__ void k_tail(Params P) {
  int b = blockIdx.z;
  int role = blockIdx.y;
  int Vb = vb_of(b), Mb = Vb + NSAMP, E = 3 * Vb;
  int i = blockIdx.x * blockDim.x + threadIdx.x;
  double v = 0.0;

  if (role == 0) {                      // chamfer combine
    if (blockIdx.x >= 112) return;
    if (i < NGT) {
      float gx = P.gt[3 * i], gy = P.gt[3 * i + 1], gz = P.gt[3 * i + 2];
      float gg = gx * gx + gy * gy + gz * gz;
      float d = gg - 2.0f * dec_f(g_best1[b][i]);
      v += (3000.0 / NGT) * (double)d;
    }
    if (i < Mb) {
      const float* src = (i < Vb) ? (P.pred[b] + 3 * i) : (g_samp[b] + 3 * (i - Vb));
      float px = src[0], py = src[1], pz = src[2];
      float pp = px * px + py * py + pz * pz;
      float m = -3.4e38f;
      #pragma unroll
      for (int s = 0; s < SEGS; s++) m = fmaxf(m, g_d2seg[b][s][i]);
      float d = pp - 2.0f * m;
      v += (3000.0 * 0.55 / Mb) * (double)d;
    }
  } else if (role == 1) {               // edge + normal
    if (i < E) {
      const int* eg = P.edges[b];
      int e0 = eg[2 * i], e1 = eg[2 * i + 1];
      const float* pr = P.pred[b];
      float dx = pr[3 * e0]     - pr[3 * e1];
      float dy = pr[3 * e0 + 1] - pr[3 * e1 + 1];
      float dz = pr[3 * e0 + 2] - pr[3 * e1 + 2];
      float esq = dx * dx + dy * dy + dz * dz;
      float inv = 1.0f / fmaxf(sqrtf(esq), 1e-12f);
      int gi = g_imin[b][e0];
      const float* nn = P.gtn + 3 * gi;
      float nx = nn[0], ny = nn[1], nz = nn[2];
      float ninv = 1.0f / fmaxf(sqrtf(nx * nx + ny * ny + nz * nz), 1e-12f);
      float dot = (dx * nx + dy * ny + dz * nz) * inv * ninv;
      v = (359.0 / E) * (double)esq + (0.5 / E) * (double)fabsf(dot);
    }
  } else {                              // laplacian + move
    if (blockIdx.x >= 81) return;
    if (i < Vb) {
      float lapc = (b == 0) ? 0.2f : 1.0f;
      const int* row = P.lap[b] + 10 * i;
      float cnt = (float)row[9];
      const float* pr = P.pred[b];
      const float* bf = P.bef[b];
      float spx = 0, spy = 0, spz = 0, sbx = 0, sby = 0, sbz = 0;
      #pragma unroll
      for (int k = 0; k < 8; k++) {
        int n = row[k];
        if (n >= 0) {
          spx += pr[3 * n]; spy += pr[3 * n + 1]; spz += pr[3 * n + 2];
          sbx += bf[3 * n]; sby += bf[3 * n + 1]; sbz += bf[3 * n + 2];
        }
      }
      float lbx = bf[3 * i]     - sbx / cnt;
      float lby = bf[3 * i + 1] - sby / cnt;
      float lbz = bf[3 * i + 2] - sbz / cnt;
      float lpx = pr[3 * i]     - spx / cnt;
      float lpy = pr[3 * i + 1] - spy / cnt;
      float lpz = pr[3 * i + 2] - spz / cnt;
      float d0 = lbx - lpx, d1 = lby - lpy, d2 = lbz - lpz;
      float lapsq = d0 * d0 + d1 * d1 + d2 * d2;
      float m0 = bf[3 * i] - pr[3 * i];
      float m1 = bf[3 * i + 1] - pr[3 * i + 1];
      float m2 = bf[3 * i + 2] - pr[3 * i + 2];
      float movesq = m0 * m0 + m1 * m1 + m2 * m2;
      v = (1500.0 * (double)lapc / Vb) * (double)lapsq;
      if (b > 0) v += (50.0 * (double)lapc / Vb) * (double)movesq;
    }
  }
  block_add(v);
}

__global__ void k_final(Params P) { P.out[0] = (float)g_loss; }

// ---------------- launch ----------------
extern "C" void kernel_launch(void* const* d_in, const int* in_sizes, int n_in,
                              void* d_out, int out_size) {
  (void)in_sizes; (void)n_in; (void)out_size;
  Params p;
  p.gt  = (const float*)d_in[0];
  p.gtn = (const float*)d_in[1];
  for (int i = 0; i < 3; i++) {
    p.pred[i]  = (const float*)d_in[2 + 5 * i];
    p.bef[i]   = (const float*)d_in[3 + 5 * i];
    p.edges[i] = (const int*)  d_in[4 + 5 * i];
    p.faces[i] = (const int*)  d_in[5 + 5 * i];
    p.lap[i]   = (const int*)  d_in[6 + 5 * i];
  }
  p.out = (float*)d_out;

  dim3 bs(128);
  k_reset <<<dim3(48), 256>>>();
  k_sample<<<dim3(32, 1, 3),    bs>>>(p);
  k_cham  <<<dim3(28, SEGS, 6), bs>>>(p);   // fused d1+d2, 4 pts/thread
  k_rescan<<<dim3(3362),        bs>>>(p);   // warp per vertex (13446 warps)
  k_tail  <<<dim3(241, 3, 3),   bs>>>(p);   // reduce / edge / lap
  k_final <<<1, 1>>>(p);
}

// round 5
// speedup vs baseline: 4.4529x; 1.0349x over previous
#include <cuda_runtime.h>

#define NGT   8000
#define NSAMP 4000
#define TILE  128
#define MAXV  10242
#define MAXM  (MAXV + NSAMP)
#define SEGS  16
#define NPT   4
#define PTSPB (TILE * NPT)   // 512 outer points per block
typedef unsigned long long ull;

static __device__ double g_loss;
static __device__ int    g_imin[3][MAXV];
static __device__ unsigned g_best1[3][NGT];          // encoded max-score, gt->pred
static __device__ float    g_d2seg[3][SEGS][MAXM];   // per-segment max score, pred->gt
static __device__ float4   g_gtp[NGT];               // gt packed (x,y,z,-0.5|q|^2)
static __device__ float4   g_pp[3][MAXM];            // pred+samples packed

struct Params {
  const float* gt;  const float* gtn;
  const float* pred[3]; const float* bef[3];
  const int*   edges[3]; const int* faces[3]; const int* lap[3];
  float* out;
};

__device__ __forceinline__ int vb_of(int b) { return b == 0 ? 642 : (b == 1 ? 2562 : 10242); }

__device__ __forceinline__ unsigned enc_f(float f) {
  unsigned u = __float_as_uint(f);
  return (u & 0x80000000u) ? ~u : (u | 0x80000000u);
}
__device__ __forceinline__ float dec_f(unsigned u) {
  unsigned b = (u & 0x80000000u) ? (u ^ 0x80000000u) : ~u;
  return __uint_as_float(b);
}

// ---- packed f32x2 helpers ----
__device__ __forceinline__ ull ffma2(ull a, ull b, ull c) {
  ull d;
  asm("fma.rn.f32x2 %0, %1, %2, %3;" : "=l"(d) : "l"(a), "l"(b), "l"(c));
  return d;
}
__device__ __forceinline__ ull dup2(float v) {
  ull r; unsigned u = __float_as_uint(v);
  asm("mov.b64 %0, {%1, %1};" : "=l"(r) : "r"(u));
  return r;
}
__device__ __forceinline__ void unpk(ull v, float& lo, float& hi) {
  unsigned l, h;
  asm("mov.b64 {%0, %1}, %2;" : "=r"(l), "=r"(h) : "l"(v));
  lo = __uint_as_float(l); hi = __uint_as_float(h);
}

// pinned-rounding score pieces (bit-identical everywhere)
__device__ __forceinline__ float wneg_of(float qx, float qy, float qz) {
  return -0.5f * __fmaf_rn(qx, qx, __fmaf_rn(qy, qy, __fmul_rn(qz, qz)));
}
__device__ __forceinline__ float score_of(float x, float y, float z,
                                          float qx, float qy, float qz, float w) {
  return __fmaf_rn(x, qx, __fmaf_rn(y, qy, __fmaf_rn(z, qz, w)));
}

// ---------------- threefry2x32 (exact JAX block) ----------------
__device__ __forceinline__ void tf(unsigned k0, unsigned k1,
                                   unsigned x0, unsigned x1,
                                   unsigned& o0, unsigned& o1) {
  unsigned ks2 = k0 ^ k1 ^ 0x1BD11BDAu;
  x0 += k0; x1 += k1;
#define R_(r) { x0 += x1; x1 = (x1 << (r)) | (x1 >> (32 - (r))); x1 ^= x0; }
  R_(13) R_(15) R_(26) R_(6)  x0 += k1;  x1 += ks2 + 1u;
  R_(17) R_(29) R_(16) R_(24) x0 += ks2; x1 += k0  + 2u;
  R_(13) R_(15) R_(26) R_(6)  x0 += k0;  x1 += k1  + 3u;
  R_(17) R_(29) R_(16) R_(24) x0 += k1;  x1 += ks2 + 4u;
  R_(13) R_(15) R_(26) R_(6)  x0 += ks2; x1 += k0  + 5u;
#undef R_
  o0 = x0; o1 = x1;
}

__device__ __forceinline__ void block_add(double v) {
  #pragma unroll
  for (int o = 16; o; o >>= 1) v += __shfl_down_sync(0xffffffffu, v, o);
  __shared__ double ws[4];
  int lane = threadIdx.x & 31, w = threadIdx.x >> 5;
  if (lane == 0) ws[w] = v;
  __syncthreads();
  if (w == 0) {
    double t = (lane < 4) ? ws[lane] : 0.0;
    t += __shfl_down_sync(0xffffffffu, t, 2);
    t += __shfl_down_sync(0xffffffffu, t, 1);
    if (lane == 0) atomicAdd(&g_loss, t);
  }
}

// ---------------- prep: sample + pack + reset, role by blockIdx.y ----------------
__global__ void k_prep(Params P) {
  int role = blockIdx.y;
  int b = blockIdx.z;
  int i = blockIdx.x * blockDim.x + threadIdx.x;
  int Vb = vb_of(b);

  if (role == 0) {                       // sampling (exact JAX PRNG)
    if (i >= NSAMP) return;
    unsigned span = 2u * (unsigned)Vb;
    unsigned kb0, kb1; tf(0u, 42u, 0u, (unsigned)b, kb0, kb1);
    unsigned kf0, kf1, ku0, ku1, k10, k11, k20, k21, t0, t1, hi, lo, u0b, u1b;
    tf(kb0, kb1, 0u, 0u, kf0, kf1);
    tf(kb0, kb1, 0u, 1u, ku0, ku1);
    tf(kf0, kf1, 0u, 0u, k10, k11);
    tf(kf0, kf1, 0u, 1u, k20, k21);
    tf(k10, k11, 0u, (unsigned)i, t0, t1);            hi  = t0 ^ t1;
    tf(k20, k21, 0u, (unsigned)i, t0, t1);            lo  = t0 ^ t1;
    tf(ku0, ku1, 0u, (unsigned)(2 * i),     t0, t1);  u0b = t0 ^ t1;
    tf(ku0, ku1, 0u, (unsigned)(2 * i + 1), t0, t1);  u1b = t0 ^ t1;
    unsigned m = 65536u % span; m = (m * m) % span;
    int fidx = (int)(((hi % span) * m + (lo % span)) % span);
    float u0 = __uint_as_float((u0b >> 9) | 0x3F800000u) - 1.0f;
    float u1 = __uint_as_float((u1b >> 9) | 0x3F800000u) - 1.0f;
    float r1 = sqrtf(u0);
    float w0 = 1.0f - r1, w1 = r1 * (1.0f - u1), w2 = r1 * u1;
    const int* f = P.faces[b] + 3 * fidx;
    const float* pr = P.pred[b];
    int v0 = f[0], v1 = f[1], v2 = f[2];
    float sx = w0 * pr[3 * v0]     + w1 * pr[3 * v1]     + w2 * pr[3 * v2];
    float sy = w0 * pr[3 * v0 + 1] + w1 * pr[3 * v1 + 1] + w2 * pr[3 * v2 + 1];
    float sz = w0 * pr[3 * v0 + 2] + w1 * pr[3 * v1 + 2] + w2 * pr[3 * v2 + 2];
    g_pp[b][Vb + i] = make_float4(sx, sy, sz, wneg_of(sx, sy, sz));
  } else if (role == 1) {                // pack vertices
    if (i < Vb) {
      const float* s = P.pred[b] + 3 * i;
      float x = s[0], y = s[1], z = s[2];
      g_pp[b][i] = make_float4(x, y, z, wneg_of(x, y, z));
    }
  } else if (role == 2) {                // pack gt (b==0 only)
    if (b == 0 && i < NGT) {
      const float* s = P.gt + 3 * i;
      float x = s[0], y = s[1], z = s[2];
      g_gtp[i] = make_float4(x, y, z, wneg_of(x, y, z));
    }
  } else {                               // reset
    if (i < NGT) g_best1[b][i] = 0u;
    if (b == 0 && i == 0) g_loss = 0.0;
  }
}

// ---------------- fused chamfer (both directions, split-K) ----------------
// z in [0,6): b = z%3, dir = z/3.  dir0: outer=gt, inner=pred_all (min only)
//                                  dir1: outer=pred_all, inner=gt (per-seg max)
__global__ void __launch_bounds__(TILE, 8) k_cham(Params P) {
  int z = blockIdx.z;
  int b = (z >= 3) ? z - 3 : z;
  bool d2 = z >= 3;
  int Vb = vb_of(b), Mb = Vb + NSAMP;
  int Nout = d2 ? Mb : NGT;
  int Nin  = d2 ? NGT : Mb;

  int base_pt = blockIdx.x * PTSPB;
  if (base_pt >= Nout) return;
  int tid = threadIdx.x;

  const float4* outPk = d2 ? g_pp[b] : g_gtp;
  const float4* inPk  = d2 ? g_gtp  : g_pp[b];

  ull xd[NPT], yd[NPT], zd[NPT]; float bsL[NPT], bsH[NPT];
  #pragma unroll
  for (int k = 0; k < NPT; k++) {
    int j = base_pt + k * TILE + tid;
    float4 q = outPk[(j < Nout) ? j : 0];
    xd[k] = dup2(q.x); yd[k] = dup2(q.y); zd[k] = dup2(q.z);
    bsL[k] = -3.4e38f; bsH[k] = -3.4e38f;
  }

  int segLen = (Nin + SEGS - 1) / SEGS;
  int segLo = blockIdx.y * segLen;
  int segHi = min(segLo + segLen, Nin);

  __shared__ float4 sxy[TILE / 2], szw[TILE / 2];

  for (int tb = segLo; tb < segHi; tb += TILE) {
    {
      int j = tb + tid;
      float4 q = (j < segHi) ? inPk[j] : make_float4(0.f, 0.f, 0.f, -3.4e38f);
      int h = tid >> 1, o = tid & 1;
      ((float*)sxy)[4 * h + o]     = q.x;
      ((float*)sxy)[4 * h + 2 + o] = q.y;
      ((float*)szw)[4 * h + o]     = q.z;
      ((float*)szw)[4 * h + 2 + o] = q.w;
    }
    __syncthreads();
    #pragma unroll 8
    for (int t2 = 0; t2 < TILE / 2; t2++) {
      ull x01 = ((const ull*)sxy)[2 * t2], y01 = ((const ull*)sxy)[2 * t2 + 1];
      ull z01 = ((const ull*)szw)[2 * t2], w01 = ((const ull*)szw)[2 * t2 + 1];
      #pragma unroll
      for (int k = 0; k < NPT; k++) {
        ull s2 = ffma2(xd[k], x01, ffma2(yd[k], y01, ffma2(zd[k], z01, w01)));
        float lo, hi; unpk(s2, lo, hi);
        bsL[k] = fmaxf(bsL[k], lo);
        bsH[k] = fmaxf(bsH[k], hi);
      }
    }
    __syncthreads();
  }
  #pragma unroll
  for (int k = 0; k < NPT; k++) {
    int j = base_pt + k * TILE + tid;
    float bs = fmaxf(bsL[k], bsH[k]);
    if (j < Nout) {
      if (d2) g_d2seg[b][blockIdx.y][j] = bs;
      else    atomicMax(&g_best1[b][j], enc_f(bs));
    }
  }
}

// ---------------- rescan: warp-per-vertex first-argmax ----------------
__global__ void k_rescan(Params P) {
  int gw = (blockIdx.x * blockDim.x + threadIdx.x) >> 5;
  int lane = threadIdx.x & 31;
  int b, v;
  if (gw < 642)             { b = 0; v = gw; }
  else if (gw < 642 + 2562) { b = 1; v = gw - 642; }
  else if (gw < 13446)      { b = 2; v = gw - 3204; }
  else return;

  float best = -3.4e38f; int bseg = 0;
  #pragma unroll
  for (int s = 0; s < SEGS; s++) {
    float val = g_d2seg[b][s][v];
    if (val > best) { best = val; bseg = s; }
  }
  const int segLen = (NGT + SEGS - 1) / SEGS;   // 500
  int lo = bseg * segLen, hi = min(lo + segLen, NGT);

  float4 pv = g_pp[b][v];
  float x = pv.x, y = pv.y, z = pv.z;
  float bsv = -3.4e38f; int bi = 0x7fffffff;
  for (int j = lo + lane; j < hi; j += 32) {
    float4 q = __ldg(&g_gtp[j]);
    float s = score_of(x, y, z, q.x, q.y, q.z, q.w);
    if (s > bsv || (s == bsv && j < bi)) { bsv = s; bi = j; }
  }
  #pragma unroll
  for (int o = 16; o; o >>= 1) {
    float so = __shfl_down_sync(0xffffffffu, bsv, o);
    int   io = __shfl_down_sync(0xffffffffu, bi,  o);
    if (so > bsv || (so == bsv && io < bi)) { bsv = so; bi = io; }
  }
  if (lane == 0) g_imin[b][v] = bi;
}

// ---------------- fused tail: reduce / edge+normal / lap+move ----------------
__global__ void k_tail(Params P) {
  int b = blockIdx.z;
  int role = blockIdx.y;
  int Vb = vb_of(b), Mb = Vb + NSAMP, E = 3 * Vb;
  int i = blockIdx.x * blockDim.x + threadIdx.x;
  double v = 0.0;

  if (role == 0) {                      // chamfer combine
    if (blockIdx.x >= 112) return;
    if (i < NGT) {
      float gg = -2.0f * g_gtp[i].w;
      float d = gg - 2.0f * dec_f(g_best1[b][i]);
      v += (3000.0 / NGT) * (double)d;
    }
    if (i < Mb) {
      float pp = -2.0f * g_pp[b][i].w;
      float m = -3.4e38f;
      #pragma unroll
      for (int s = 0; s < SEGS; s++) m = fmaxf(m, g_d2seg[b][s][i]);
      float d = pp - 2.0f * m;
      v += (3000.0 * 0.55 / Mb) * (double)d;
    }
  } else if (role == 1) {               // edge + normal
    if (i < E) {
      const int* eg = P.edges[b];
      int e0 = eg[2 * i], e1 = eg[2 * i + 1];
      float4 p0 = g_pp[b][e0], p1 = g_pp[b][e1];
      float dx = p0.x - p1.x, dy = p0.y - p1.y, dz = p0.z - p1.z;
      float esq = dx * dx + dy * dy + dz * dz;
      float inv = 1.0f / fmaxf(sqrtf(esq), 1e-12f);
      int gi = g_imin[b][e0];
      const float* nn = P.gtn + 3 * gi;
      float nx = nn[0], ny = nn[1], nz = nn[2];
      float ninv = 1.0f / fmaxf(sqrtf(nx * nx + ny * ny + nz * nz), 1e-12f);
      float dot = (dx * nx + dy * ny + dz * nz) * inv * ninv;
      v = (359.0 / E) * (double)esq + (0.5 / E) * (double)fabsf(dot);
    }
  } else {                              // laplacian + move
    if (blockIdx.x >= 81) return;
    if (i < Vb) {
      float lapc = (b == 0) ? 0.2f : 1.0f;
      const int* row = P.lap[b] + 10 * i;
      float cnt = (float)row[9];
      const float* pr = P.pred[b];
      const float* bf = P.bef[b];
      float spx = 0, spy = 0, spz = 0, sbx = 0, sby = 0, sbz = 0;
      #pragma unroll
      for (int k = 0; k < 8; k++) {
        int n = row[k];
        if (n >= 0) {
          spx += pr[3 * n]; spy += pr[3 * n + 1]; spz += pr[3 * n + 2];
          sbx += bf[3 * n]; sby += bf[3 * n + 1]; sbz += bf[3 * n + 2];
        }
      }
      float lbx = bf[3 * i]     - sbx / cnt;
      float lby = bf[3 * i + 1] - sby / cnt;
      float lbz = bf[3 * i + 2] - sbz / cnt;
      float lpx = pr[3 * i]     - spx / cnt;
      float lpy = pr[3 * i + 1] - spy / cnt;
      float lpz = pr[3 * i + 2] - spz / cnt;
      float d0 = lbx - lpx, d1 = lby - lpy, d2 = lbz - lpz;
      float lapsq = d0 * d0 + d1 * d1 + d2 * d2;
      float m0 = bf[3 * i] - pr[3 * i];
      float m1 = bf[3 * i + 1] - pr[3 * i + 1];
      float m2 = bf[3 * i + 2] - pr[3 * i + 2];
      float movesq = m0 * m0 + m1 * m1 + m2 * m2;
      v = (1500.0 * (double)lapc / Vb) * (double)lapsq;
      if (b > 0) v += (50.0 * (double)lapc / Vb) * (double)movesq;
    }
  }
  block_add(v);
}

__global__ void k_final(Params P) { P.out[0] = (float)g_loss; }

// ---------------- launch ----------------
extern "C" void kernel_launch(void* const* d_in, const int* in_sizes, int n_in,
                              void* d_out, int out_size) {
  (void)in_sizes; (void)n_in; (void)out_size;
  Params p;
  p.gt  = (const float*)d_in[0];
  p.gtn = (const float*)d_in[1];
  for (int i = 0; i < 3; i++) {
    p.pred[i]  = (const float*)d_in[2 + 5 * i];
    p.bef[i]   = (const float*)d_in[3 + 5 * i];
    p.edges[i] = (const int*)  d_in[4 + 5 * i];
    p.faces[i] = (const int*)  d_in[5 + 5 * i];
    p.lap[i]   = (const int*)  d_in[6 + 5 * i];
  }
  p.out = (float*)d_out;

  dim3 bs(128);
  k_prep  <<<dim3(81, 4, 3),    bs>>>(p);   // sample / pack pred / pack gt / reset
  k_cham  <<<dim3(28, SEGS, 6), bs>>>(p);   // fused d1+d2, 4 pts/thread
  k_rescan<<<dim3(3362),        bs>>>(p);   // warp per vertex (13446 warps)
  k_tail  <<<dim3(241, 3, 3),   bs>>>(p);   // reduce / edge / lap
  k_final <<<1, 1>>>(p);
}